// round 12
// baseline (speedup 1.0000x reference)
#include <cuda_runtime.h>
#include <cuda_bf16.h>
#include <mma.h>
#include <cstdint>

using namespace nvcuda;

#define BB 4
#define CC 128
#define NN 4096
#define LDH 136   // bf16 tile leading dim (pad 8)
#define LDF 132   // fp32 tile leading dim (pad 4)

typedef wmma::fragment<wmma::matrix_a,16,16,16,__nv_bfloat16,wmma::row_major> FragA;
typedef wmma::fragment<wmma::matrix_b,16,16,16,__nv_bfloat16,wmma::col_major> FragBc;
typedef wmma::fragment<wmma::accumulator,16,16,16,float> FragC;

// ---------------- device scratch ----------------
__device__ __align__(16) __nv_bfloat16 d_wqkv[3*CC*CC];
__device__ __align__(16) __nv_bfloat16 d_wproj[CC*CC];
__device__ float d_scl[BB*CC];
__device__ float d_sht[BB*CC];
__device__ __align__(16) __nv_bfloat16 d_q[BB*NN*CC];   // [b][n][c]
__device__ __align__(16) __nv_bfloat16 d_k[BB*NN*CC];   // [b][n][c]
__device__ __align__(16) __nv_bfloat16 d_v[BB*NN*CC];   // [b][n][c]
__device__ __align__(16) __nv_bfloat16 d_o[BB*NN*CC];   // [b][n][c]

// ================= low-level helpers (all sm_80-legal) =================
__device__ __forceinline__ uint32_t smem_u32(const void* p) {
    uint32_t a;
    asm("{ .reg .u64 t; cvta.to.shared.u64 t, %1; cvt.u32.u64 %0, t; }" : "=r"(a) : "l"(p));
    return a;
}
__device__ __forceinline__ void cpa16(uint32_t d, const void* s) {
    asm volatile("cp.async.cg.shared.global [%0], [%1], 16;" :: "r"(d), "l"(s));
}
#define CP_COMMIT() asm volatile("cp.async.commit_group;" ::: "memory")
#define CP_WAIT(n)  asm volatile("cp.async.wait_group %0;" :: "n"(n) : "memory")

__device__ __forceinline__ void ldsm4(uint32_t r[4], uint32_t a) {
    asm volatile("ldmatrix.sync.aligned.m8n8.x4.shared.b16 {%0,%1,%2,%3}, [%4];"
        : "=r"(r[0]), "=r"(r[1]), "=r"(r[2]), "=r"(r[3]) : "r"(a));
}
__device__ __forceinline__ void ldsm4t(uint32_t r[4], uint32_t a) {
    asm volatile("ldmatrix.sync.aligned.m8n8.x4.trans.shared.b16 {%0,%1,%2,%3}, [%4];"
        : "=r"(r[0]), "=r"(r[1]), "=r"(r[2]), "=r"(r[3]) : "r"(a));
}
__device__ __forceinline__ void mma16816(float c[4], const uint32_t a[4], const uint32_t b[2]) {
    asm volatile("mma.sync.aligned.m16n8k16.row.col.f32.bf16.bf16.f32 "
        "{%0,%1,%2,%3}, {%4,%5,%6,%7}, {%8,%9}, {%0,%1,%2,%3};"
        : "+f"(c[0]), "+f"(c[1]), "+f"(c[2]), "+f"(c[3])
        : "r"(a[0]), "r"(a[1]), "r"(a[2]), "r"(a[3]), "r"(b[0]), "r"(b[1]));
}
__device__ __forceinline__ float ex2f(float x) {
    float y;
    asm("ex2.approx.f32 %0, %1;" : "=f"(y) : "f"(x));
    return y;
}
__device__ __forceinline__ uint32_t packbf2(float a, float b) {
    __nv_bfloat162 h = __floats2bfloat162_rn(a, b);
    return *(uint32_t*)&h;
}

// ---------------- K0: convert weights to bf16 ----------------
__global__ __launch_bounds__(256) void k_convert(const float* __restrict__ qkvw,
                                                 const float* __restrict__ projw) {
    int i = blockIdx.x*256 + threadIdx.x;
    if (i < 3*CC*CC) d_wqkv[i]  = __float2bfloat16(qkvw[i]);
    if (i < CC*CC)   d_wproj[i] = __float2bfloat16(projw[i]);
}

// ---------------- K1: GroupNorm stats ----------------
__global__ __launch_bounds__(256) void k_gnstats(const float* __restrict__ x,
                                                 const float* __restrict__ nw,
                                                 const float* __restrict__ nb) {
    int b = blockIdx.x >> 3, g = blockIdx.x & 7;
    const float4* p = (const float4*)(x + ((size_t)(b*CC) + g*16)*NN);
    const int M4 = (16*NN)/4;
    float s = 0.f, s2 = 0.f;
    for (int i = threadIdx.x; i < M4; i += 256) {
        float4 v = p[i];
        s  += v.x + v.y + v.z + v.w;
        s2 += v.x*v.x + v.y*v.y + v.z*v.z + v.w*v.w;
    }
    __shared__ float rs[8], rs2[8];
    #pragma unroll
    for (int o = 16; o; o >>= 1) {
        s  += __shfl_xor_sync(0xffffffffu, s,  o);
        s2 += __shfl_xor_sync(0xffffffffu, s2, o);
    }
    if ((threadIdx.x & 31) == 0) { rs[threadIdx.x>>5] = s; rs2[threadIdx.x>>5] = s2; }
    __syncthreads();
    __shared__ float smean, srstd;
    if (threadIdx.x == 0) {
        float ts = 0.f, ts2 = 0.f;
        #pragma unroll
        for (int i = 0; i < 8; i++) { ts += rs[i]; ts2 += rs2[i]; }
        const float M = 16.f*NN;
        float mean = ts / M;
        float var  = ts2 / M - mean*mean;
        smean = mean;
        srstd = rsqrtf(var + 1e-5f);
    }
    __syncthreads();
    if (threadIdx.x < 16) {
        int c = g*16 + threadIdx.x;
        float w = nw[c];
        d_scl[b*CC + c] = srstd * w;
        d_sht[b*CC + c] = nb[c] - smean * srstd * w;
    }
}

// ---------------- K2: fused normalize + QKV GEMM (wmma) ----------------
__global__ __launch_bounds__(256) void k_qkv(const float* __restrict__ x,
                                             const float* __restrict__ qkvb) {
    extern __shared__ char sm[];
    __nv_bfloat16* As = (__nv_bfloat16*)sm;
    __nv_bfloat16* Bs = As + 128*LDH;
    float*         Cs = (float*)(Bs + 128*LDH);
    const int nt = blockIdx.x, b = blockIdx.y, tid = threadIdx.x;
    const int nbase = nt*128;

    {
        int c = tid >> 1, nh = tid & 1;
        const float4* xp = (const float4*)(x + ((size_t)(b*CC) + c)*NN + nbase + nh*64);
        float sc = d_scl[b*CC + c], sh = d_sht[b*CC + c];
        #pragma unroll
        for (int i = 0; i < 16; i++) {
            float4 v = xp[i];
            int n = nh*64 + i*4;
            As[(n+0)*LDH + c] = __float2bfloat16(v.x*sc + sh);
            As[(n+1)*LDH + c] = __float2bfloat16(v.y*sc + sh);
            As[(n+2)*LDH + c] = __float2bfloat16(v.z*sc + sh);
            As[(n+3)*LDH + c] = __float2bfloat16(v.w*sc + sh);
        }
    }

    const int w = tid >> 5, wr = w >> 1, wc = w & 1;
    for (int ot = 0; ot < 3; ot++) {
        __syncthreads();
        {
            int o = tid >> 1, ch = tid & 1;
            const uint2* wp = (const uint2*)(d_wqkv + (ot*128 + o)*CC + ch*64);
            uint2* dp = (uint2*)(Bs + o*LDH + ch*64);
            #pragma unroll
            for (int i = 0; i < 16; i++) dp[i] = wp[i];
        }
        __syncthreads();
        #pragma unroll
        for (int i = 0; i < 2; i++) {
            FragC acc[4];
            #pragma unroll
            for (int jj = 0; jj < 4; jj++) wmma::fill_fragment(acc[jj], 0.f);
            #pragma unroll
            for (int k = 0; k < 8; k++) {
                FragA a; wmma::load_matrix_sync(a, As + (wr*32 + i*16)*LDH + k*16, LDH);
                #pragma unroll
                for (int jj = 0; jj < 4; jj++) {
                    FragBc bfr; wmma::load_matrix_sync(bfr, Bs + (wc*64 + jj*16)*LDH + k*16, LDH);
                    wmma::mma_sync(acc[jj], a, bfr, acc[jj]);
                }
            }
            #pragma unroll
            for (int jj = 0; jj < 4; jj++)
                wmma::store_matrix_sync(Cs + (wr*32 + i*16)*LDF + wc*64 + jj*16, acc[jj], LDF, wmma::mem_row_major);
        }
        __syncthreads();
        __nv_bfloat16* dst = (ot == 0) ? d_q : (ot == 1) ? d_k : d_v;
        {
            int n = tid >> 1, oh = tid & 1;
            __nv_bfloat16* op = dst + ((size_t)(b*NN) + nbase + n)*CC + oh*64;
            const float* cp = Cs + n*LDF + oh*64;
            const float* bp = qkvb + ot*128 + oh*64;
            #pragma unroll
            for (int i = 0; i < 64; i++) op[i] = __float2bfloat16(cp[i] + bp[i]);
        }
    }
}

// ---------------- K3: attention — register FA2 on mma.m16n8k16 ----------------
// CTA: 128 thr (4 warps), q-tile 64 (16 rows/warp), kv-tile 64, double-buffered cp.async.
// 2 CTAs co-resident per SM (smem 80KB, regs ~48K total) -> independent barrier
// domains keep the tensor pipe fed while one CTA waits.
// smem: sQ 16KB | sK0 16KB | sK1 16KB | sV0 16KB | sV1 16KB = 80KB.

__device__ __forceinline__ void load_tile64(uint32_t sbase, const __nv_bfloat16* g, int tid) {
    // 64 rows x 128 cols bf16 = 1024 16B-chunks; 8 per thread; swizzle chunk ^= row&7
    #pragma unroll
    for (int j = 0; j < 8; j++) {
        int id = tid + 128*j;
        int row = id >> 4, c = id & 15;
        cpa16(sbase + row*256 + ((c ^ (row & 7)) << 4), g + row*CC + c*8);
    }
}

__global__ __launch_bounds__(128) void k_attn() {
    extern __shared__ char sm[];
    const int tid = threadIdx.x, lane = tid & 31, w = tid >> 5;
    const int qt = blockIdx.x, b = blockIdx.y;
    const uint32_t sb = smem_u32(sm);
    const uint32_t sQ = sb;
    const uint32_t sK[2] = { sb + 16384, sb + 32768 };
    const uint32_t sV[2] = { sb + 49152, sb + 65536 };

    const __nv_bfloat16* gq = d_q + ((size_t)(b*NN) + qt*64)*CC;
    const __nv_bfloat16* gk = d_k + (size_t)(b*NN)*CC;
    const __nv_bfloat16* gv = d_v + (size_t)(b*NN)*CC;

    // ---- prologue loads: Q + tile0 (group0), tile1 (group1) ----
    load_tile64(sQ, gq, tid);
    load_tile64(sK[0], gk, tid);
    load_tile64(sV[0], gv, tid);
    CP_COMMIT();
    load_tile64(sK[1], gk + (size_t)64*CC, tid);
    load_tile64(sV[1], gv + (size_t)64*CC, tid);
    CP_COMMIT();

    const int r8 = lane & 7;            // row-within-8
    const int hs = (lane >> 3) & 1;     // tile half-select
    const int q16 = lane >> 4;          // chunk select

    CP_WAIT(1);                          // Q + tile0 resident
    __syncthreads();

    // ---- Q fragments (A-operand, row-major), k-frag kb covers d[16kb,16kb+16) ----
    uint32_t qf[8][4];
    #pragma unroll
    for (int kb = 0; kb < 8; kb++) {
        int row = w*16 + hs*8 + r8;
        int ch = 2*kb + q16;
        ldsm4(qf[kb], sQ + row*256 + ((ch ^ r8) << 4));
    }

    float o[16][4];
    #pragma unroll
    for (int nb = 0; nb < 16; nb++)
        #pragma unroll
        for (int e = 0; e < 4; e++) o[nb][e] = 0.f;
    float l0 = 0.f, l1 = 0.f;
    const float sl2e = 0.12751744f;     // (1/sqrt(128)) * log2(e)

    #pragma unroll 1
    for (int it = 0; it < 64; it++) {
        const int bi = it & 1;
        if (it > 0) { CP_WAIT(1); __syncthreads(); }

        // ---- S = Q K^T (this warp's 16 rows x 64 kv) ----
        float sc[8][4];
        #pragma unroll
        for (int nb = 0; nb < 8; nb++) {
            #pragma unroll
            for (int e = 0; e < 4; e++) sc[nb][e] = 0.f;
            #pragma unroll
            for (int kb2 = 0; kb2 < 4; kb2++) {
                uint32_t kf[4];
                int row = nb*8 + r8;
                int ch = 4*kb2 + (lane >> 3);
                ldsm4(kf, sK[bi] + row*256 + ((ch ^ r8) << 4));
                mma16816(sc[nb], qf[2*kb2],     kf);
                mma16816(sc[nb], qf[2*kb2 + 1], kf + 2);
            }
        }

        // ---- exp (no-max: |s*scale| bounded), row-sum partials, pack P ----
        #pragma unroll
        for (int nb = 0; nb < 8; nb++) {
            sc[nb][0] = ex2f(sc[nb][0]*sl2e);
            sc[nb][1] = ex2f(sc[nb][1]*sl2e);
            sc[nb][2] = ex2f(sc[nb][2]*sl2e);
            sc[nb][3] = ex2f(sc[nb][3]*sl2e);
            l0 += sc[nb][0] + sc[nb][1];
            l1 += sc[nb][2] + sc[nb][3];
        }
        uint32_t pk[4][4];
        #pragma unroll
        for (int kb = 0; kb < 4; kb++) {
            pk[kb][0] = packbf2(sc[2*kb][0],   sc[2*kb][1]);
            pk[kb][1] = packbf2(sc[2*kb][2],   sc[2*kb][3]);
            pk[kb][2] = packbf2(sc[2*kb+1][0], sc[2*kb+1][1]);
            pk[kb][3] = packbf2(sc[2*kb+1][2], sc[2*kb+1][3]);
        }

        // ---- O += P V ----
        #pragma unroll
        for (int nb2 = 0; nb2 < 8; nb2++) {
            #pragma unroll
            for (int kb = 0; kb < 4; kb++) {
                uint32_t vf[4];
                int row = kb*16 + hs*8 + r8;
                int ch = 2*nb2 + q16;
                ldsm4t(vf, sV[bi] + row*256 + ((ch ^ r8) << 4));
                mma16816(o[2*nb2],     pk[kb], vf);
                mma16816(o[2*nb2 + 1], pk[kb], vf + 2);
            }
        }

        __syncthreads();   // all warps done reading buf bi
        if (it + 2 < 64) {
            load_tile64(sK[bi], gk + (size_t)(it + 2)*64*CC, tid);
            load_tile64(sV[bi], gv + (size_t)(it + 2)*64*CC, tid);
        }
        CP_COMMIT();
    }

    // ---- finalize: quad-reduce row sums, normalize, store ----
    l0 += __shfl_xor_sync(0xffffffffu, l0, 1);
    l0 += __shfl_xor_sync(0xffffffffu, l0, 2);
    l1 += __shfl_xor_sync(0xffffffffu, l1, 1);
    l1 += __shfl_xor_sync(0xffffffffu, l1, 2);
    const float i0 = 1.f / l0, i1 = 1.f / l1;

    const int g = lane >> 2, c0 = (lane & 3)*2;
    __nv_bfloat16* ob = d_o + ((size_t)(b*NN) + qt*64 + w*16)*CC;
    #pragma unroll
    for (int nb = 0; nb < 16; nb++) {
        uint32_t p0 = packbf2(o[nb][0]*i0, o[nb][1]*i0);
        uint32_t p1 = packbf2(o[nb][2]*i1, o[nb][3]*i1);
        *(uint32_t*)(ob + (size_t)g*CC       + nb*8 + c0) = p0;
        *(uint32_t*)(ob + (size_t)(g + 8)*CC + nb*8 + c0) = p1;
    }
}

// ---------------- K4: proj GEMM + bias + residual (wmma) ----------------
__global__ __launch_bounds__(256) void k_proj(const float* __restrict__ x,
                                              const float* __restrict__ projb,
                                              float* __restrict__ out) {
    extern __shared__ char sm[];
    __nv_bfloat16* As = (__nv_bfloat16*)sm;
    __nv_bfloat16* Bs = As + 128*LDH;
    float*         Cs = (float*)(Bs + 128*LDH);
    const int nt = blockIdx.x, b = blockIdx.y, tid = threadIdx.x;
    const int nbase = nt*128;

    {
        const uint2* ag = (const uint2*)(d_o + ((size_t)(b*NN) + nbase)*CC);
        for (int i = tid; i < 128*32; i += 256) {
            int r = i >> 5, cv = i & 31;
            *(uint2*)&As[r*LDH + cv*4] = ag[r*32 + cv];
        }
    }
    {
        int o = tid >> 1, ch = tid & 1;
        const uint2* wp = (const uint2*)(d_wproj + o*CC + ch*64);
        uint2* dp = (uint2*)(Bs + o*LDH + ch*64);
        #pragma unroll
        for (int i = 0; i < 16; i++) dp[i] = wp[i];
    }
    __syncthreads();

    const int w = tid >> 5, wr = w >> 1, wc = w & 1;
    #pragma unroll
    for (int i = 0; i < 2; i++) {
        FragC acc[4];
        #pragma unroll
        for (int jj = 0; jj < 4; jj++) wmma::fill_fragment(acc[jj], 0.f);
        #pragma unroll
        for (int k = 0; k < 8; k++) {
            FragA a; wmma::load_matrix_sync(a, As + (wr*32 + i*16)*LDH + k*16, LDH);
            #pragma unroll
            for (int jj = 0; jj < 4; jj++) {
                FragBc bfr; wmma::load_matrix_sync(bfr, Bs + (wc*64 + jj*16)*LDH + k*16, LDH);
                wmma::mma_sync(acc[jj], a, bfr, acc[jj]);
            }
        }
        #pragma unroll
        for (int jj = 0; jj < 4; jj++)
            wmma::store_matrix_sync(Cs + (wr*32 + i*16)*LDF + wc*64 + jj*16, acc[jj], LDF, wmma::mem_row_major);
    }
    __syncthreads();
    {
        int c = tid >> 1, nh = tid & 1;
        const float* xp = x + ((size_t)(b*CC) + c)*NN + nbase + nh*64;
        float* op = out + ((size_t)(b*CC) + c)*NN + nbase + nh*64;
        float pb = projb[c];
        #pragma unroll
        for (int i = 0; i < 64; i++)
            op[i] = xp[i] + pb + Cs[(nh*64 + i)*LDF + c];
    }
}

// ---------------- launcher ----------------
extern "C" void kernel_launch(void* const* d_in, const int* in_sizes, int n_in,
                              void* d_out, int out_size) {
    const float* x     = (const float*)d_in[0];
    const float* nw    = (const float*)d_in[1];
    const float* nb    = (const float*)d_in[2];
    const float* qkvw  = (const float*)d_in[3];
    const float* qkvb  = (const float*)d_in[4];
    const float* projw = (const float*)d_in[5];
    const float* projb = (const float*)d_in[6];
    float* out = (float*)d_out;

    const int SM_GEMM = 2*128*LDH*2 + 128*LDF*4;     // 137216
    const int SM_ATTN = 5*16384;                     // 81920

    cudaFuncSetAttribute(k_qkv,  cudaFuncAttributeMaxDynamicSharedMemorySize, SM_GEMM);
    cudaFuncSetAttribute(k_attn, cudaFuncAttributeMaxDynamicSharedMemorySize, SM_ATTN);
    cudaFuncSetAttribute(k_proj, cudaFuncAttributeMaxDynamicSharedMemorySize, SM_GEMM);

    k_convert<<<192, 256>>>(qkvw, projw);
    k_gnstats<<<32, 256>>>(x, nw, nb);
    k_qkv<<<dim3(32, BB), 256, SM_GEMM>>>(x, qkvb);
    k_attn<<<dim3(64, BB), 128, SM_ATTN>>>();
    k_proj<<<dim3(32, BB), 256, SM_GEMM>>>(x, projb, out);
}

// round 13
// speedup vs baseline: 1.0564x; 1.0564x over previous
#include <cuda_runtime.h>
#include <cuda_bf16.h>
#include <mma.h>
#include <cstdint>

using namespace nvcuda;

#define BB 4
#define CC 128
#define NN 4096
#define LDH 136   // bf16 tile leading dim (pad 8)
#define LDF 132   // fp32 tile leading dim (pad 4)

typedef wmma::fragment<wmma::matrix_a,16,16,16,__nv_bfloat16,wmma::row_major> FragA;
typedef wmma::fragment<wmma::matrix_b,16,16,16,__nv_bfloat16,wmma::col_major> FragBc;
typedef wmma::fragment<wmma::accumulator,16,16,16,float> FragC;

// ---------------- device scratch ----------------
__device__ __align__(16) __nv_bfloat16 d_wqkv[3*CC*CC];
__device__ __align__(16) __nv_bfloat16 d_wproj[CC*CC];
__device__ float d_scl[BB*CC];
__device__ float d_sht[BB*CC];
__device__ __align__(16) __nv_bfloat16 d_q[BB*NN*CC];   // [b][n][c]
__device__ __align__(16) __nv_bfloat16 d_k[BB*NN*CC];   // [b][n][c]
__device__ __align__(16) __nv_bfloat16 d_v[BB*NN*CC];   // [b][n][c]
__device__ __align__(16) float d_op[2*BB*NN*CC];        // kv-split partial O (fp32)
__device__ float d_l[2*BB*NN];                          // kv-split partial row sums

// ================= low-level helpers =================
__device__ __forceinline__ uint32_t smem_u32(const void* p) {
    uint32_t a;
    asm("{ .reg .u64 t; cvta.to.shared.u64 t, %1; cvt.u32.u64 %0, t; }" : "=r"(a) : "l"(p));
    return a;
}
__device__ __forceinline__ void cpa16(uint32_t d, const void* s) {
    asm volatile("cp.async.cg.shared.global [%0], [%1], 16;" :: "r"(d), "l"(s));
}
#define CP_COMMIT() asm volatile("cp.async.commit_group;" ::: "memory")
#define CP_WAIT(n)  asm volatile("cp.async.wait_group %0;" :: "n"(n) : "memory")

__device__ __forceinline__ void ldsm4(uint32_t r[4], uint32_t a) {
    asm volatile("ldmatrix.sync.aligned.m8n8.x4.shared.b16 {%0,%1,%2,%3}, [%4];"
        : "=r"(r[0]), "=r"(r[1]), "=r"(r[2]), "=r"(r[3]) : "r"(a));
}
__device__ __forceinline__ void ldsm4t(uint32_t r[4], uint32_t a) {
    asm volatile("ldmatrix.sync.aligned.m8n8.x4.trans.shared.b16 {%0,%1,%2,%3}, [%4];"
        : "=r"(r[0]), "=r"(r[1]), "=r"(r[2]), "=r"(r[3]) : "r"(a));
}
__device__ __forceinline__ void mma16816(float c[4], const uint32_t a[4], const uint32_t b[2]) {
    asm volatile("mma.sync.aligned.m16n8k16.row.col.f32.bf16.bf16.f32 "
        "{%0,%1,%2,%3}, {%4,%5,%6,%7}, {%8,%9}, {%0,%1,%2,%3};"
        : "+f"(c[0]), "+f"(c[1]), "+f"(c[2]), "+f"(c[3])
        : "r"(a[0]), "r"(a[1]), "r"(a[2]), "r"(a[3]), "r"(b[0]), "r"(b[1]));
}
__device__ __forceinline__ float ex2f(float x) {
    float y;
    asm("ex2.approx.f32 %0, %1;" : "=f"(y) : "f"(x));
    return y;
}
__device__ __forceinline__ uint32_t packbf2(float a, float b) {
    __nv_bfloat162 h = __floats2bfloat162_rn(a, b);
    return *(uint32_t*)&h;
}

// ---------------- K0: convert weights to bf16 ----------------
__global__ __launch_bounds__(256) void k_convert(const float* __restrict__ qkvw,
                                                 const float* __restrict__ projw) {
    int i = blockIdx.x*256 + threadIdx.x;
    if (i < 3*CC*CC) d_wqkv[i]  = __float2bfloat16(qkvw[i]);
    if (i < CC*CC)   d_wproj[i] = __float2bfloat16(projw[i]);
}

// ---------------- K1: GroupNorm stats ----------------
__global__ __launch_bounds__(256) void k_gnstats(const float* __restrict__ x,
                                                 const float* __restrict__ nw,
                                                 const float* __restrict__ nb) {
    int b = blockIdx.x >> 3, g = blockIdx.x & 7;
    const float4* p = (const float4*)(x + ((size_t)(b*CC) + g*16)*NN);
    const int M4 = (16*NN)/4;
    float s = 0.f, s2 = 0.f;
    for (int i = threadIdx.x; i < M4; i += 256) {
        float4 v = p[i];
        s  += v.x + v.y + v.z + v.w;
        s2 += v.x*v.x + v.y*v.y + v.z*v.z + v.w*v.w;
    }
    __shared__ float rs[8], rs2[8];
    #pragma unroll
    for (int o = 16; o; o >>= 1) {
        s  += __shfl_xor_sync(0xffffffffu, s,  o);
        s2 += __shfl_xor_sync(0xffffffffu, s2, o);
    }
    if ((threadIdx.x & 31) == 0) { rs[threadIdx.x>>5] = s; rs2[threadIdx.x>>5] = s2; }
    __syncthreads();
    __shared__ float smean, srstd;
    if (threadIdx.x == 0) {
        float ts = 0.f, ts2 = 0.f;
        #pragma unroll
        for (int i = 0; i < 8; i++) { ts += rs[i]; ts2 += rs2[i]; }
        const float M = 16.f*NN;
        float mean = ts / M;
        float var  = ts2 / M - mean*mean;
        smean = mean;
        srstd = rsqrtf(var + 1e-5f);
    }
    __syncthreads();
    if (threadIdx.x < 16) {
        int c = g*16 + threadIdx.x;
        float w = nw[c];
        d_scl[b*CC + c] = srstd * w;
        d_sht[b*CC + c] = nb[c] - smean * srstd * w;
    }
}

// ---------------- K2: fused normalize + QKV GEMM (wmma) ----------------
__global__ __launch_bounds__(256) void k_qkv(const float* __restrict__ x,
                                             const float* __restrict__ qkvb) {
    extern __shared__ char sm[];
    __nv_bfloat16* As = (__nv_bfloat16*)sm;
    __nv_bfloat16* Bs = As + 128*LDH;
    float*         Cs = (float*)(Bs + 128*LDH);
    const int nt = blockIdx.x, b = blockIdx.y, tid = threadIdx.x;
    const int nbase = nt*128;

    {
        int c = tid >> 1, nh = tid & 1;
        const float4* xp = (const float4*)(x + ((size_t)(b*CC) + c)*NN + nbase + nh*64);
        float sc = d_scl[b*CC + c], sh = d_sht[b*CC + c];
        #pragma unroll
        for (int i = 0; i < 16; i++) {
            float4 v = xp[i];
            int n = nh*64 + i*4;
            As[(n+0)*LDH + c] = __float2bfloat16(v.x*sc + sh);
            As[(n+1)*LDH + c] = __float2bfloat16(v.y*sc + sh);
            As[(n+2)*LDH + c] = __float2bfloat16(v.z*sc + sh);
            As[(n+3)*LDH + c] = __float2bfloat16(v.w*sc + sh);
        }
    }

    const int w = tid >> 5, wr = w >> 1, wc = w & 1;
    for (int ot = 0; ot < 3; ot++) {
        __syncthreads();
        {
            int o = tid >> 1, ch = tid & 1;
            const uint2* wp = (const uint2*)(d_wqkv + (ot*128 + o)*CC + ch*64);
            uint2* dp = (uint2*)(Bs + o*LDH + ch*64);
            #pragma unroll
            for (int i = 0; i < 16; i++) dp[i] = wp[i];
        }
        __syncthreads();
        #pragma unroll
        for (int i = 0; i < 2; i++) {
            FragC acc[4];
            #pragma unroll
            for (int jj = 0; jj < 4; jj++) wmma::fill_fragment(acc[jj], 0.f);
            #pragma unroll
            for (int k = 0; k < 8; k++) {
                FragA a; wmma::load_matrix_sync(a, As + (wr*32 + i*16)*LDH + k*16, LDH);
                #pragma unroll
                for (int jj = 0; jj < 4; jj++) {
                    FragBc bfr; wmma::load_matrix_sync(bfr, Bs + (wc*64 + jj*16)*LDH + k*16, LDH);
                    wmma::mma_sync(acc[jj], a, bfr, acc[jj]);
                }
            }
            #pragma unroll
            for (int jj = 0; jj < 4; jj++)
                wmma::store_matrix_sync(Cs + (wr*32 + i*16)*LDF + wc*64 + jj*16, acc[jj], LDF, wmma::mem_row_major);
        }
        __syncthreads();
        __nv_bfloat16* dst = (ot == 0) ? d_q : (ot == 1) ? d_k : d_v;
        {
            int n = tid >> 1, oh = tid & 1;
            __nv_bfloat16* op = dst + ((size_t)(b*NN) + nbase + n)*CC + oh*64;
            const float* cp = Cs + n*LDF + oh*64;
            const float* bp = qkvb + ot*128 + oh*64;
            #pragma unroll
            for (int i = 0; i < 64; i++) op[i] = __float2bfloat16(cp[i] + bp[i]);
        }
    }
}

// ---------------- K3: attention — register FA2, 32 q-rows/warp, kv-split 2 ----------------
// CTA: 256 thr (8 warps), q-tile 256 (32 rows/warp), kv-tile 64, kv range split in 2.
// Each K/V fragment now feeds 2 row-fragments -> LDSM bytes per mma halved.
// smem: sQ 64KB | sK0 16KB | sK1 16KB | sV0 16KB | sV1 16KB = 128KB.
// Output: unnormalized fp32 partial O + partial row-sum l (combined in k_proj).

__device__ __forceinline__ void load_tile64(uint32_t sbase, const __nv_bfloat16* g, int tid) {
    // 64 rows x 128 cols bf16 = 1024 16B-chunks; 4 per thread (256 thr)
    #pragma unroll
    for (int j = 0; j < 4; j++) {
        int id = tid + 256*j;
        int row = id >> 4, c = id & 15;
        cpa16(sbase + row*256 + ((c ^ (row & 7)) << 4), g + row*CC + c*8);
    }
}

__global__ __launch_bounds__(256) void k_attn() {
    extern __shared__ char sm[];
    const int tid = threadIdx.x, lane = tid & 31, w = tid >> 5;
    const int qt = blockIdx.x, ks = blockIdx.y, b = blockIdx.z;
    const uint32_t sb = smem_u32(sm);
    const uint32_t sQ = sb;
    const uint32_t sK[2] = { sb + 65536, sb + 81920 };
    const uint32_t sV[2] = { sb + 98304, sb + 114688 };

    const __nv_bfloat16* gq = d_q + ((size_t)(b*NN) + qt*256)*CC;
    const __nv_bfloat16* gk = d_k + ((size_t)(b*NN) + ks*2048)*CC;
    const __nv_bfloat16* gv = d_v + ((size_t)(b*NN) + ks*2048)*CC;

    // ---- prologue: Q (256x128) + kv tiles 0,1 ----
    #pragma unroll
    for (int j = 0; j < 16; j++) {
        int id = tid + 256*j;
        int row = id >> 4, c = id & 15;
        cpa16(sQ + row*256 + ((c ^ (row & 7)) << 4), gq + row*CC + c*8);
    }
    load_tile64(sK[0], gk, tid);
    load_tile64(sV[0], gv, tid);
    CP_COMMIT();
    load_tile64(sK[1], gk + (size_t)64*CC, tid);
    load_tile64(sV[1], gv + (size_t)64*CC, tid);
    CP_COMMIT();

    const int r8 = lane & 7;
    const int hs = (lane >> 3) & 1;
    const int q16 = lane >> 4;

    CP_WAIT(1);
    __syncthreads();

    // ---- Q fragments: 2 row-frags x 8 k-frags, rows w*32 + rf*16 + ... ----
    uint32_t qf[2][8][4];
    #pragma unroll
    for (int rf = 0; rf < 2; rf++)
        #pragma unroll
        for (int kb = 0; kb < 8; kb++) {
            int row = w*32 + rf*16 + hs*8 + r8;
            int ch = 2*kb + q16;
            ldsm4(qf[rf][kb], sQ + row*256 + ((ch ^ r8) << 4));
        }

    float o[2][16][4];
    #pragma unroll
    for (int rf = 0; rf < 2; rf++)
        #pragma unroll
        for (int cf = 0; cf < 16; cf++)
            #pragma unroll
            for (int e = 0; e < 4; e++) o[rf][cf][e] = 0.f;
    float l[2][2] = {{0.f, 0.f}, {0.f, 0.f}};
    const float sl2e = 0.12751744f;     // (1/sqrt(128)) * log2(e)

    #pragma unroll 1
    for (int it = 0; it < 32; it++) {
        const int bi = it & 1;
        if (it > 0) { CP_WAIT(1); __syncthreads(); }

        #pragma unroll
        for (int s = 0; s < 4; s++) {       // kv 16-slices within 64-tile
            // ---- S(32q x 16kv) ----
            float sc[2][2][4];
            #pragma unroll
            for (int rf = 0; rf < 2; rf++)
                #pragma unroll
                for (int nh = 0; nh < 2; nh++)
                    #pragma unroll
                    for (int e = 0; e < 4; e++) sc[rf][nh][e] = 0.f;
            #pragma unroll
            for (int kb2 = 0; kb2 < 4; kb2++) {
                uint32_t kf0[4], kf1[4];
                int ch = 4*kb2 + (lane >> 3);
                ldsm4(kf0, sK[bi] + (s*16 +     r8)*256 + ((ch ^ r8) << 4));
                ldsm4(kf1, sK[bi] + (s*16 + 8 + r8)*256 + ((ch ^ r8) << 4));
                #pragma unroll
                for (int rf = 0; rf < 2; rf++) {
                    mma16816(sc[rf][0], qf[rf][2*kb2],     kf0);
                    mma16816(sc[rf][0], qf[rf][2*kb2 + 1], kf0 + 2);
                    mma16816(sc[rf][1], qf[rf][2*kb2],     kf1);
                    mma16816(sc[rf][1], qf[rf][2*kb2 + 1], kf1 + 2);
                }
            }

            // ---- exp + row-sum + pack P (A-frag for PV) ----
            uint32_t pk[2][4];
            #pragma unroll
            for (int rf = 0; rf < 2; rf++) {
                #pragma unroll
                for (int nh = 0; nh < 2; nh++)
                    #pragma unroll
                    for (int e = 0; e < 4; e++)
                        sc[rf][nh][e] = ex2f(sc[rf][nh][e]*sl2e);
                l[rf][0] += sc[rf][0][0] + sc[rf][0][1] + sc[rf][1][0] + sc[rf][1][1];
                l[rf][1] += sc[rf][0][2] + sc[rf][0][3] + sc[rf][1][2] + sc[rf][1][3];
                pk[rf][0] = packbf2(sc[rf][0][0], sc[rf][0][1]);
                pk[rf][1] = packbf2(sc[rf][0][2], sc[rf][0][3]);
                pk[rf][2] = packbf2(sc[rf][1][0], sc[rf][1][1]);
                pk[rf][3] = packbf2(sc[rf][1][2], sc[rf][1][3]);
            }

            // ---- O += P(32x16) V(16x128) ----
            #pragma unroll
            for (int cf = 0; cf < 8; cf++) {
                uint32_t vf[4];
                int ch = 2*cf + q16;
                ldsm4t(vf, sV[bi] + (s*16 + hs*8 + r8)*256 + ((ch ^ r8) << 4));
                #pragma unroll
                for (int rf = 0; rf < 2; rf++) {
                    mma16816(o[rf][2*cf],     pk[rf], vf);
                    mma16816(o[rf][2*cf + 1], pk[rf], vf + 2);
                }
            }
        }

        __syncthreads();
        if (it + 2 < 32) {
            load_tile64(sK[bi], gk + (size_t)(it + 2)*64*CC, tid);
            load_tile64(sV[bi], gv + (size_t)(it + 2)*64*CC, tid);
        }
        CP_COMMIT();
    }

    // ---- epilogue: write unnormalized fp32 partial O + partial l ----
    const int grp = lane >> 2, tc = lane & 3;
    float* op = d_op + (((size_t)ks*BB + b)*NN + qt*256 + w*32)*CC;
    #pragma unroll
    for (int rf = 0; rf < 2; rf++)
        #pragma unroll
        for (int cf = 0; cf < 16; cf++) {
            int col = cf*8 + 2*tc;
            *(float2*)(op + (rf*16 + grp    )*CC + col) = make_float2(o[rf][cf][0], o[rf][cf][1]);
            *(float2*)(op + (rf*16 + grp + 8)*CC + col) = make_float2(o[rf][cf][2], o[rf][cf][3]);
        }
    #pragma unroll
    for (int rf = 0; rf < 2; rf++)
        #pragma unroll
        for (int h = 0; h < 2; h++) {
            float v = l[rf][h];
            v += __shfl_xor_sync(0xffffffffu, v, 1);
            v += __shfl_xor_sync(0xffffffffu, v, 2);
            if (tc == 0)
                d_l[((size_t)ks*BB + b)*NN + qt*256 + w*32 + rf*16 + grp + 8*h] = v;
        }
}

// ---------------- K4: combine kv-splits + proj GEMM + bias + residual ----------------
__global__ __launch_bounds__(256) void k_proj(const float* __restrict__ x,
                                              const float* __restrict__ projb,
                                              float* __restrict__ out) {
    extern __shared__ char sm[];
    __nv_bfloat16* As = (__nv_bfloat16*)sm;
    __nv_bfloat16* Bs = As + 128*LDH;
    float*         Cs = (float*)(Bs + 128*LDH);
    const int nt = blockIdx.x, b = blockIdx.y, tid = threadIdx.x;
    const int nbase = nt*128;

    // A = (O0 + O1) / (l0 + l1), converted to bf16
    {
        int n = tid >> 1, hh = tid & 1;
        size_t base = ((size_t)(b*NN) + nbase + n)*CC + hh*64;
        const float4* p0 = (const float4*)(d_op + base);
        const float4* p1 = (const float4*)(d_op + (size_t)BB*NN*CC + base);
        float inv = 1.f / (d_l[(size_t)b*NN + nbase + n] +
                           d_l[(size_t)BB*NN + b*NN + nbase + n]);
        __nv_bfloat16* ap = As + n*LDH + hh*64;
        #pragma unroll
        for (int i = 0; i < 16; i++) {
            float4 a = p0[i], c = p1[i];
            ap[4*i+0] = __float2bfloat16((a.x + c.x)*inv);
            ap[4*i+1] = __float2bfloat16((a.y + c.y)*inv);
            ap[4*i+2] = __float2bfloat16((a.z + c.z)*inv);
            ap[4*i+3] = __float2bfloat16((a.w + c.w)*inv);
        }
    }
    {
        int o = tid >> 1, ch = tid & 1;
        const uint2* wp = (const uint2*)(d_wproj + o*CC + ch*64);
        uint2* dp = (uint2*)(Bs + o*LDH + ch*64);
        #pragma unroll
        for (int i = 0; i < 16; i++) dp[i] = wp[i];
    }
    __syncthreads();

    const int w = tid >> 5, wr = w >> 1, wc = w & 1;
    #pragma unroll
    for (int i = 0; i < 2; i++) {
        FragC acc[4];
        #pragma unroll
        for (int jj = 0; jj < 4; jj++) wmma::fill_fragment(acc[jj], 0.f);
        #pragma unroll
        for (int k = 0; k < 8; k++) {
            FragA a; wmma::load_matrix_sync(a, As + (wr*32 + i*16)*LDH + k*16, LDH);
            #pragma unroll
            for (int jj = 0; jj < 4; jj++) {
                FragBc bfr; wmma::load_matrix_sync(bfr, Bs + (wc*64 + jj*16)*LDH + k*16, LDH);
                wmma::mma_sync(acc[jj], a, bfr, acc[jj]);
            }
        }
        #pragma unroll
        for (int jj = 0; jj < 4; jj++)
            wmma::store_matrix_sync(Cs + (wr*32 + i*16)*LDF + wc*64 + jj*16, acc[jj], LDF, wmma::mem_row_major);
    }
    __syncthreads();
    {
        int c = tid >> 1, nh = tid & 1;
        const float* xp = x + ((size_t)(b*CC) + c)*NN + nbase + nh*64;
        float* op = out + ((size_t)(b*CC) + c)*NN + nbase + nh*64;
        float pb = projb[c];
        #pragma unroll
        for (int i = 0; i < 64; i++)
            op[i] = xp[i] + pb + Cs[(nh*64 + i)*LDF + c];
    }
}

// ---------------- launcher ----------------
extern "C" void kernel_launch(void* const* d_in, const int* in_sizes, int n_in,
                              void* d_out, int out_size) {
    const float* x     = (const float*)d_in[0];
    const float* nw    = (const float*)d_in[1];
    const float* nb    = (const float*)d_in[2];
    const float* qkvw  = (const float*)d_in[3];
    const float* qkvb  = (const float*)d_in[4];
    const float* projw = (const float*)d_in[5];
    const float* projb = (const float*)d_in[6];
    float* out = (float*)d_out;

    const int SM_GEMM = 2*128*LDH*2 + 128*LDF*4;     // 137216
    const int SM_ATTN = 65536 + 4*16384;             // 131072

    cudaFuncSetAttribute(k_qkv,  cudaFuncAttributeMaxDynamicSharedMemorySize, SM_GEMM);
    cudaFuncSetAttribute(k_attn, cudaFuncAttributeMaxDynamicSharedMemorySize, SM_ATTN);
    cudaFuncSetAttribute(k_proj, cudaFuncAttributeMaxDynamicSharedMemorySize, SM_GEMM);

    k_convert<<<192, 256>>>(qkvw, projw);
    k_gnstats<<<32, 256>>>(x, nw, nb);
    k_qkv<<<dim3(32, BB), 256, SM_GEMM>>>(x, qkvb);
    k_attn<<<dim3(16, 2, BB), 256, SM_ATTN>>>();
    k_proj<<<dim3(32, BB), 256, SM_GEMM>>>(x, projb, out);
}

// round 14
// speedup vs baseline: 1.1123x; 1.0529x over previous
#include <cuda_runtime.h>
#include <cuda_bf16.h>
#include <mma.h>
#include <cstdint>

using namespace nvcuda;

#define BB 4
#define CC 128
#define NN 4096
#define LDH 136   // bf16 tile leading dim (pad 8)
#define LDF 132   // fp32 tile leading dim (pad 4)

typedef wmma::fragment<wmma::matrix_a,16,16,16,__nv_bfloat16,wmma::row_major> FragA;
typedef wmma::fragment<wmma::matrix_b,16,16,16,__nv_bfloat16,wmma::col_major> FragBc;
typedef wmma::fragment<wmma::accumulator,16,16,16,float> FragC;

// ---------------- device scratch ----------------
__device__ __align__(16) __nv_bfloat16 d_wqkv[3*CC*CC];
__device__ __align__(16) __nv_bfloat16 d_wproj[CC*CC];
__device__ float d_scl[BB*CC];
__device__ float d_sht[BB*CC];
__device__ __align__(16) __nv_bfloat16 d_q[BB*NN*CC];   // [b][n][c]
__device__ __align__(16) __nv_bfloat16 d_k[BB*NN*CC];   // [b][n][c]
__device__ __align__(16) __nv_bfloat16 d_v[BB*NN*CC];   // [b][n][c]
__device__ __align__(16) float d_op[2*BB*NN*CC];        // kv-split partial O (fp32)
__device__ float d_l[2*BB*NN];                          // kv-split partial row sums

// ================= low-level helpers =================
__device__ __forceinline__ uint32_t smem_u32(const void* p) {
    uint32_t a;
    asm("{ .reg .u64 t; cvta.to.shared.u64 t, %1; cvt.u32.u64 %0, t; }" : "=r"(a) : "l"(p));
    return a;
}
__device__ __forceinline__ void cpa16(uint32_t d, const void* s) {
    asm volatile("cp.async.cg.shared.global [%0], [%1], 16;" :: "r"(d), "l"(s));
}
#define CP_COMMIT() asm volatile("cp.async.commit_group;" ::: "memory")
#define CP_WAIT(n)  asm volatile("cp.async.wait_group %0;" :: "n"(n) : "memory")

__device__ __forceinline__ void ldsm4(uint32_t r[4], uint32_t a) {
    asm volatile("ldmatrix.sync.aligned.m8n8.x4.shared.b16 {%0,%1,%2,%3}, [%4];"
        : "=r"(r[0]), "=r"(r[1]), "=r"(r[2]), "=r"(r[3]) : "r"(a));
}
__device__ __forceinline__ void ldsm4t(uint32_t r[4], uint32_t a) {
    asm volatile("ldmatrix.sync.aligned.m8n8.x4.trans.shared.b16 {%0,%1,%2,%3}, [%4];"
        : "=r"(r[0]), "=r"(r[1]), "=r"(r[2]), "=r"(r[3]) : "r"(a));
}
__device__ __forceinline__ void mma16816(float c[4], const uint32_t a[4], const uint32_t b[2]) {
    asm volatile("mma.sync.aligned.m16n8k16.row.col.f32.bf16.bf16.f32 "
        "{%0,%1,%2,%3}, {%4,%5,%6,%7}, {%8,%9}, {%0,%1,%2,%3};"
        : "+f"(c[0]), "+f"(c[1]), "+f"(c[2]), "+f"(c[3])
        : "r"(a[0]), "r"(a[1]), "r"(a[2]), "r"(a[3]), "r"(b[0]), "r"(b[1]));
}
__device__ __forceinline__ float ex2f(float x) {
    float y;
    asm("ex2.approx.f32 %0, %1;" : "=f"(y) : "f"(x));
    return y;
}
__device__ __forceinline__ uint32_t packbf2(float a, float b) {
    __nv_bfloat162 h = __floats2bfloat162_rn(a, b);
    return *(uint32_t*)&h;
}

// ---------------- K0+K1 merged: weight convert + GroupNorm stats ----------------
__global__ __launch_bounds__(256) void k_prep(const float* __restrict__ x,
                                              const float* __restrict__ nw,
                                              const float* __restrict__ nb,
                                              const float* __restrict__ qkvw,
                                              const float* __restrict__ projw) {
    __shared__ float rs[8], rs2[8];
    __shared__ float smean, srstd;
    if (blockIdx.x < 192) {
        int i = blockIdx.x*256 + threadIdx.x;
        if (i < 3*CC*CC) d_wqkv[i]  = __float2bfloat16(qkvw[i]);
        if (i < CC*CC)   d_wproj[i] = __float2bfloat16(projw[i]);
        return;
    }
    int bg = blockIdx.x - 192;
    int b = bg >> 3, g = bg & 7;
    const float4* p = (const float4*)(x + ((size_t)(b*CC) + g*16)*NN);
    const int M4 = (16*NN)/4;
    float s = 0.f, s2 = 0.f;
    for (int i = threadIdx.x; i < M4; i += 256) {
        float4 v = p[i];
        s  += v.x + v.y + v.z + v.w;
        s2 += v.x*v.x + v.y*v.y + v.z*v.z + v.w*v.w;
    }
    #pragma unroll
    for (int o = 16; o; o >>= 1) {
        s  += __shfl_xor_sync(0xffffffffu, s,  o);
        s2 += __shfl_xor_sync(0xffffffffu, s2, o);
    }
    if ((threadIdx.x & 31) == 0) { rs[threadIdx.x>>5] = s; rs2[threadIdx.x>>5] = s2; }
    __syncthreads();
    if (threadIdx.x == 0) {
        float ts = 0.f, ts2 = 0.f;
        #pragma unroll
        for (int i = 0; i < 8; i++) { ts += rs[i]; ts2 += rs2[i]; }
        const float M = 16.f*NN;
        float mean = ts / M;
        float var  = ts2 / M - mean*mean;
        smean = mean;
        srstd = rsqrtf(var + 1e-5f);
    }
    __syncthreads();
    if (threadIdx.x < 16) {
        int c = g*16 + threadIdx.x;
        float w = nw[c];
        d_scl[b*CC + c] = srstd * w;
        d_sht[b*CC + c] = nb[c] - smean * srstd * w;
    }
}

// ---------------- K2: fused normalize + QKV GEMM (wmma) ----------------
__global__ __launch_bounds__(256) void k_qkv(const float* __restrict__ x,
                                             const float* __restrict__ qkvb) {
    extern __shared__ char sm[];
    __nv_bfloat16* As = (__nv_bfloat16*)sm;
    __nv_bfloat16* Bs = As + 128*LDH;
    float*         Cs = (float*)(Bs + 128*LDH);
    const int nt = blockIdx.x, b = blockIdx.y, tid = threadIdx.x;
    const int nbase = nt*128;

    {
        int c = tid >> 1, nh = tid & 1;
        const float4* xp = (const float4*)(x + ((size_t)(b*CC) + c)*NN + nbase + nh*64);
        float sc = d_scl[b*CC + c], sh = d_sht[b*CC + c];
        #pragma unroll
        for (int i = 0; i < 16; i++) {
            float4 v = xp[i];
            int n = nh*64 + i*4;
            As[(n+0)*LDH + c] = __float2bfloat16(v.x*sc + sh);
            As[(n+1)*LDH + c] = __float2bfloat16(v.y*sc + sh);
            As[(n+2)*LDH + c] = __float2bfloat16(v.z*sc + sh);
            As[(n+3)*LDH + c] = __float2bfloat16(v.w*sc + sh);
        }
    }

    const int w = tid >> 5, wr = w >> 1, wc = w & 1;
    for (int ot = 0; ot < 3; ot++) {
        __syncthreads();
        {
            int o = tid >> 1, ch = tid & 1;
            const uint2* wp = (const uint2*)(d_wqkv + (ot*128 + o)*CC + ch*64);
            uint2* dp = (uint2*)(Bs + o*LDH + ch*64);
            #pragma unroll
            for (int i = 0; i < 16; i++) dp[i] = wp[i];
        }
        __syncthreads();
        #pragma unroll
        for (int i = 0; i < 2; i++) {
            FragC acc[4];
            #pragma unroll
            for (int jj = 0; jj < 4; jj++) wmma::fill_fragment(acc[jj], 0.f);
            #pragma unroll
            for (int k = 0; k < 8; k++) {
                FragA a; wmma::load_matrix_sync(a, As + (wr*32 + i*16)*LDH + k*16, LDH);
                #pragma unroll
                for (int jj = 0; jj < 4; jj++) {
                    FragBc bfr; wmma::load_matrix_sync(bfr, Bs + (wc*64 + jj*16)*LDH + k*16, LDH);
                    wmma::mma_sync(acc[jj], a, bfr, acc[jj]);
                }
            }
            #pragma unroll
            for (int jj = 0; jj < 4; jj++)
                wmma::store_matrix_sync(Cs + (wr*32 + i*16)*LDF + wc*64 + jj*16, acc[jj], LDF, wmma::mem_row_major);
        }
        __syncthreads();
        __nv_bfloat16* dst = (ot == 0) ? d_q : (ot == 1) ? d_k : d_v;
        {
            int n = tid >> 1, oh = tid & 1;
            __nv_bfloat16* op = dst + ((size_t)(b*NN) + nbase + n)*CC + oh*64;
            const float* cp = Cs + n*LDF + oh*64;
            const float* bp = qkvb + ot*128 + oh*64;
            #pragma unroll
            for (int i = 0; i < 64; i++) op[i] = __float2bfloat16(cp[i] + bp[i]);
        }
    }
}

// ---------------- K3: attention — register FA2, pipelined slices ----------------
// CTA: 256 thr (8 warps), q-tile 256 (32 rows/warp), kv-tile 128, kv-split 2.
// smem: sQ 64KB | sK0 32KB | sK1 32KB | sV0 32KB | sV1 32KB = 192KB.
// Inner loop: 8 slices of 16 kv; S(s+1) issued between exp(s) and PV(s)
// so independent tensor work covers the softmax dependency chain.

__device__ __forceinline__ void load_tile128(uint32_t sbase, const __nv_bfloat16* g, int tid) {
    // 128 rows x 128 cols bf16 = 2048 16B-chunks; 8 per thread (256 thr)
    #pragma unroll
    for (int j = 0; j < 8; j++) {
        int id = tid + 256*j;
        int row = id >> 4, c = id & 15;
        cpa16(sbase + row*256 + ((c ^ (row & 7)) << 4), g + row*CC + c*8);
    }
}

__device__ __forceinline__ void compute_S(uint32_t sKb, int s, int lane,
                                          const uint32_t qf[2][8][4],
                                          float sc[2][2][4]) {
    const int r8 = lane & 7;
    #pragma unroll
    for (int rf = 0; rf < 2; rf++)
        #pragma unroll
        for (int nh = 0; nh < 2; nh++)
            #pragma unroll
            for (int e = 0; e < 4; e++) sc[rf][nh][e] = 0.f;
    #pragma unroll
    for (int kb2 = 0; kb2 < 4; kb2++) {
        uint32_t kf0[4], kf1[4];
        int ch = 4*kb2 + (lane >> 3);
        ldsm4(kf0, sKb + (s*16 +     r8)*256 + ((ch ^ r8) << 4));
        ldsm4(kf1, sKb + (s*16 + 8 + r8)*256 + ((ch ^ r8) << 4));
        #pragma unroll
        for (int rf = 0; rf < 2; rf++) {
            mma16816(sc[rf][0], qf[rf][2*kb2],     kf0);
            mma16816(sc[rf][0], qf[rf][2*kb2 + 1], kf0 + 2);
            mma16816(sc[rf][1], qf[rf][2*kb2],     kf1);
            mma16816(sc[rf][1], qf[rf][2*kb2 + 1], kf1 + 2);
        }
    }
}

__device__ __forceinline__ void compute_PV(uint32_t sVb, int s, int lane,
                                           const uint32_t pk[2][4],
                                           float o[2][16][4]) {
    const int r8 = lane & 7, hs = (lane >> 3) & 1, q16 = lane >> 4;
    #pragma unroll
    for (int cf = 0; cf < 8; cf++) {
        uint32_t vf[4];
        int ch = 2*cf + q16;
        ldsm4t(vf, sVb + (s*16 + hs*8 + r8)*256 + ((ch ^ r8) << 4));
        #pragma unroll
        for (int rf = 0; rf < 2; rf++) {
            mma16816(o[rf][2*cf],     pk[rf], vf);
            mma16816(o[rf][2*cf + 1], pk[rf], vf + 2);
        }
    }
}

__global__ __launch_bounds__(256) void k_attn() {
    extern __shared__ char sm[];
    const int tid = threadIdx.x, lane = tid & 31, w = tid >> 5;
    const int qt = blockIdx.x, ks = blockIdx.y, b = blockIdx.z;
    const uint32_t sb = smem_u32(sm);
    const uint32_t sQ = sb;
    const uint32_t sK[2] = { sb + 65536,  sb + 98304 };
    const uint32_t sV[2] = { sb + 131072, sb + 163840 };

    const __nv_bfloat16* gq = d_q + ((size_t)(b*NN) + qt*256)*CC;
    const __nv_bfloat16* gk = d_k + ((size_t)(b*NN) + ks*2048)*CC;
    const __nv_bfloat16* gv = d_v + ((size_t)(b*NN) + ks*2048)*CC;

    // ---- prologue: Q (256x128) + kv tiles 0,1 ----
    #pragma unroll
    for (int j = 0; j < 16; j++) {
        int id = tid + 256*j;
        int row = id >> 4, c = id & 15;
        cpa16(sQ + row*256 + ((c ^ (row & 7)) << 4), gq + row*CC + c*8);
    }
    load_tile128(sK[0], gk, tid);
    load_tile128(sV[0], gv, tid);
    CP_COMMIT();
    load_tile128(sK[1], gk + (size_t)128*CC, tid);
    load_tile128(sV[1], gv + (size_t)128*CC, tid);
    CP_COMMIT();

    const int r8 = lane & 7;
    const int hs = (lane >> 3) & 1;
    const int q16 = lane >> 4;

    CP_WAIT(1);
    __syncthreads();

    // ---- Q fragments: 2 row-frags x 8 k-frags ----
    uint32_t qf[2][8][4];
    #pragma unroll
    for (int rf = 0; rf < 2; rf++)
        #pragma unroll
        for (int kb = 0; kb < 8; kb++) {
            int row = w*32 + rf*16 + hs*8 + r8;
            int ch = 2*kb + q16;
            ldsm4(qf[rf][kb], sQ + row*256 + ((ch ^ r8) << 4));
        }

    float o[2][16][4];
    #pragma unroll
    for (int rf = 0; rf < 2; rf++)
        #pragma unroll
        for (int cf = 0; cf < 16; cf++)
            #pragma unroll
            for (int e = 0; e < 4; e++) o[rf][cf][e] = 0.f;
    float l[2][2] = {{0.f, 0.f}, {0.f, 0.f}};
    const float sl2e = 0.12751744f;     // (1/sqrt(128)) * log2(e)

    #pragma unroll 1
    for (int it = 0; it < 16; it++) {
        const int bi = it & 1;
        if (it > 0) { CP_WAIT(1); __syncthreads(); }

        float sc[2][2][4];
        compute_S(sK[bi], 0, lane, qf, sc);

        #pragma unroll
        for (int s = 0; s < 8; s++) {
            // ---- exp + row-sum + pack (sc dies here) ----
            uint32_t pk[2][4];
            #pragma unroll
            for (int rf = 0; rf < 2; rf++) {
                #pragma unroll
                for (int nh = 0; nh < 2; nh++)
                    #pragma unroll
                    for (int e = 0; e < 4; e++)
                        sc[rf][nh][e] = ex2f(sc[rf][nh][e]*sl2e);
                l[rf][0] += sc[rf][0][0] + sc[rf][0][1] + sc[rf][1][0] + sc[rf][1][1];
                l[rf][1] += sc[rf][0][2] + sc[rf][0][3] + sc[rf][1][2] + sc[rf][1][3];
                pk[rf][0] = packbf2(sc[rf][0][0], sc[rf][0][1]);
                pk[rf][1] = packbf2(sc[rf][0][2], sc[rf][0][3]);
                pk[rf][2] = packbf2(sc[rf][1][0], sc[rf][1][1]);
                pk[rf][3] = packbf2(sc[rf][1][2], sc[rf][1][3]);
            }
            // ---- S(s+1): independent tensor work to overlap with PV(s) ----
            if (s < 7) compute_S(sK[bi], s + 1, lane, qf, sc);
            // ---- O += P(s) V(s) ----
            compute_PV(sV[bi], s, lane, pk, o);
        }

        __syncthreads();
        if (it + 2 < 16) {
            load_tile128(sK[bi], gk + (size_t)(it + 2)*128*CC, tid);
            load_tile128(sV[bi], gv + (size_t)(it + 2)*128*CC, tid);
        }
        CP_COMMIT();
    }

    // ---- epilogue: write unnormalized fp32 partial O + partial l ----
    const int grp = lane >> 2, tc = lane & 3;
    float* op = d_op + (((size_t)ks*BB + b)*NN + qt*256 + w*32)*CC;
    #pragma unroll
    for (int rf = 0; rf < 2; rf++)
        #pragma unroll
        for (int cf = 0; cf < 16; cf++) {
            int col = cf*8 + 2*tc;
            *(float2*)(op + (rf*16 + grp    )*CC + col) = make_float2(o[rf][cf][0], o[rf][cf][1]);
            *(float2*)(op + (rf*16 + grp + 8)*CC + col) = make_float2(o[rf][cf][2], o[rf][cf][3]);
        }
    #pragma unroll
    for (int rf = 0; rf < 2; rf++)
        #pragma unroll
        for (int h = 0; h < 2; h++) {
            float v = l[rf][h];
            v += __shfl_xor_sync(0xffffffffu, v, 1);
            v += __shfl_xor_sync(0xffffffffu, v, 2);
            if (tc == 0)
                d_l[((size_t)ks*BB + b)*NN + qt*256 + w*32 + rf*16 + grp + 8*h] = v;
        }
}

// ---------------- K4: combine kv-splits + proj GEMM + bias + residual ----------------
__global__ __launch_bounds__(256) void k_proj(const float* __restrict__ x,
                                              const float* __restrict__ projb,
                                              float* __restrict__ out) {
    extern __shared__ char sm[];
    __nv_bfloat16* As = (__nv_bfloat16*)sm;
    __nv_bfloat16* Bs = As + 128*LDH;
    float*         Cs = (float*)(Bs + 128*LDH);
    const int nt = blockIdx.x, b = blockIdx.y, tid = threadIdx.x;
    const int nbase = nt*128;

    // A = (O0 + O1) / (l0 + l1), converted to bf16
    {
        int n = tid >> 1, hh = tid & 1;
        size_t base = ((size_t)(b*NN) + nbase + n)*CC + hh*64;
        const float4* p0 = (const float4*)(d_op + base);
        const float4* p1 = (const float4*)(d_op + (size_t)BB*NN*CC + base);
        float inv = 1.f / (d_l[(size_t)b*NN + nbase + n] +
                           d_l[(size_t)BB*NN + b*NN + nbase + n]);
        __nv_bfloat16* ap = As + n*LDH + hh*64;
        #pragma unroll
        for (int i = 0; i < 16; i++) {
            float4 a = p0[i], c = p1[i];
            ap[4*i+0] = __float2bfloat16((a.x + c.x)*inv);
            ap[4*i+1] = __float2bfloat16((a.y + c.y)*inv);
            ap[4*i+2] = __float2bfloat16((a.z + c.z)*inv);
            ap[4*i+3] = __float2bfloat16((a.w + c.w)*inv);
        }
    }
    {
        int o = tid >> 1, ch = tid & 1;
        const uint2* wp = (const uint2*)(d_wproj + o*CC + ch*64);
        uint2* dp = (uint2*)(Bs + o*LDH + ch*64);
        #pragma unroll
        for (int i = 0; i < 16; i++) dp[i] = wp[i];
    }
    __syncthreads();

    const int w = tid >> 5, wr = w >> 1, wc = w & 1;
    #pragma unroll
    for (int i = 0; i < 2; i++) {
        FragC acc[4];
        #pragma unroll
        for (int jj = 0; jj < 4; jj++) wmma::fill_fragment(acc[jj], 0.f);
        #pragma unroll
        for (int k = 0; k < 8; k++) {
            FragA a; wmma::load_matrix_sync(a, As + (wr*32 + i*16)*LDH + k*16, LDH);
            #pragma unroll
            for (int jj = 0; jj < 4; jj++) {
                FragBc bfr; wmma::load_matrix_sync(bfr, Bs + (wc*64 + jj*16)*LDH + k*16, LDH);
                wmma::mma_sync(acc[jj], a, bfr, acc[jj]);
            }
        }
        #pragma unroll
        for (int jj = 0; jj < 4; jj++)
            wmma::store_matrix_sync(Cs + (wr*32 + i*16)*LDF + wc*64 + jj*16, acc[jj], LDF, wmma::mem_row_major);
    }
    __syncthreads();
    {
        int c = tid >> 1, nh = tid & 1;
        const float* xp = x + ((size_t)(b*CC) + c)*NN + nbase + nh*64;
        float* op = out + ((size_t)(b*CC) + c)*NN + nbase + nh*64;
        float pb = projb[c];
        #pragma unroll
        for (int i = 0; i < 64; i++)
            op[i] = xp[i] + pb + Cs[(nh*64 + i)*LDF + c];
    }
}

// ---------------- launcher ----------------
extern "C" void kernel_launch(void* const* d_in, const int* in_sizes, int n_in,
                              void* d_out, int out_size) {
    const float* x     = (const float*)d_in[0];
    const float* nw    = (const float*)d_in[1];
    const float* nb    = (const float*)d_in[2];
    const float* qkvw  = (const float*)d_in[3];
    const float* qkvb  = (const float*)d_in[4];
    const float* projw = (const float*)d_in[5];
    const float* projb = (const float*)d_in[6];
    float* out = (float*)d_out;

    const int SM_GEMM = 2*128*LDH*2 + 128*LDF*4;     // 137216
    const int SM_ATTN = 65536 + 4*32768;             // 196608

    cudaFuncSetAttribute(k_qkv,  cudaFuncAttributeMaxDynamicSharedMemorySize, SM_GEMM);
    cudaFuncSetAttribute(k_attn, cudaFuncAttributeMaxDynamicSharedMemorySize, SM_ATTN);
    cudaFuncSetAttribute(k_proj, cudaFuncAttributeMaxDynamicSharedMemorySize, SM_GEMM);

    k_prep<<<224, 256>>>(x, nw, nb, qkvw, projw);
    k_qkv<<<dim3(32, BB), 256, SM_GEMM>>>(x, qkvb);
    k_attn<<<dim3(16, 2, BB), 256, SM_ATTN>>>();
    k_proj<<<dim3(32, BB), 256, SM_GEMM>>>(x, projb, out);
}

// round 15
// speedup vs baseline: 1.1691x; 1.0510x over previous
#include <cuda_runtime.h>
#include <cuda_bf16.h>
#include <mma.h>
#include <cstdint>

using namespace nvcuda;

#define BB 4
#define CC 128
#define NN 4096
#define LDH 136   // bf16 tile leading dim (pad 8)
#define LDF 132   // fp32 tile leading dim (pad 4)
#define LDC 68    // fp32 col-major C leading dim (64+4)

typedef wmma::fragment<wmma::matrix_a,16,16,16,__nv_bfloat16,wmma::row_major> FragA;
typedef wmma::fragment<wmma::matrix_b,16,16,16,__nv_bfloat16,wmma::col_major> FragBc;
typedef wmma::fragment<wmma::accumulator,16,16,16,float> FragC;

// ---------------- device scratch ----------------
__device__ __align__(16) __nv_bfloat16 d_wqkv[3*CC*CC];
__device__ __align__(16) __nv_bfloat16 d_wproj[CC*CC];
__device__ float d_scl[BB*CC];
__device__ float d_sht[BB*CC];
__device__ __align__(16) __nv_bfloat16 d_q[BB*NN*CC];   // [b][n][c]
__device__ __align__(16) __nv_bfloat16 d_k[BB*NN*CC];   // [b][n][c]
__device__ __align__(16) __nv_bfloat16 d_v[BB*NN*CC];   // [b][n][c]
__device__ __align__(16) float d_op[2*BB*NN*CC];        // kv-split partial O (fp32)
__device__ float d_l[2*BB*NN];                          // kv-split partial row sums

// ================= low-level helpers =================
__device__ __forceinline__ uint32_t smem_u32(const void* p) {
    uint32_t a;
    asm("{ .reg .u64 t; cvta.to.shared.u64 t, %1; cvt.u32.u64 %0, t; }" : "=r"(a) : "l"(p));
    return a;
}
__device__ __forceinline__ void cpa16(uint32_t d, const void* s) {
    asm volatile("cp.async.cg.shared.global [%0], [%1], 16;" :: "r"(d), "l"(s));
}
#define CP_COMMIT() asm volatile("cp.async.commit_group;" ::: "memory")
#define CP_WAIT(n)  asm volatile("cp.async.wait_group %0;" :: "n"(n) : "memory")

__device__ __forceinline__ void ldsm4(uint32_t r[4], uint32_t a) {
    asm volatile("ldmatrix.sync.aligned.m8n8.x4.shared.b16 {%0,%1,%2,%3}, [%4];"
        : "=r"(r[0]), "=r"(r[1]), "=r"(r[2]), "=r"(r[3]) : "r"(a));
}
__device__ __forceinline__ void ldsm4t(uint32_t r[4], uint32_t a) {
    asm volatile("ldmatrix.sync.aligned.m8n8.x4.trans.shared.b16 {%0,%1,%2,%3}, [%4];"
        : "=r"(r[0]), "=r"(r[1]), "=r"(r[2]), "=r"(r[3]) : "r"(a));
}
__device__ __forceinline__ void mma16816(float c[4], const uint32_t a[4], const uint32_t b[2]) {
    asm volatile("mma.sync.aligned.m16n8k16.row.col.f32.bf16.bf16.f32 "
        "{%0,%1,%2,%3}, {%4,%5,%6,%7}, {%8,%9}, {%0,%1,%2,%3};"
        : "+f"(c[0]), "+f"(c[1]), "+f"(c[2]), "+f"(c[3])
        : "r"(a[0]), "r"(a[1]), "r"(a[2]), "r"(a[3]), "r"(b[0]), "r"(b[1]));
}
__device__ __forceinline__ float ex2f(float x) {
    float y;
    asm("ex2.approx.f32 %0, %1;" : "=f"(y) : "f"(x));
    return y;
}
__device__ __forceinline__ uint32_t packbf2(float a, float b) {
    __nv_bfloat162 h = __floats2bfloat162_rn(a, b);
    return *(uint32_t*)&h;
}

// ---------------- K0+K1 merged: weight convert + GroupNorm stats ----------------
__global__ __launch_bounds__(256) void k_prep(const float* __restrict__ x,
                                              const float* __restrict__ nw,
                                              const float* __restrict__ nb,
                                              const float* __restrict__ qkvw,
                                              const float* __restrict__ projw) {
    __shared__ float rs[8], rs2[8];
    __shared__ float smean, srstd;
    if (blockIdx.x < 192) {
        int i = blockIdx.x*256 + threadIdx.x;
        if (i < 3*CC*CC) d_wqkv[i]  = __float2bfloat16(qkvw[i]);
        if (i < CC*CC)   d_wproj[i] = __float2bfloat16(projw[i]);
        return;
    }
    int bg = blockIdx.x - 192;
    int b = bg >> 3, g = bg & 7;
    const float4* p = (const float4*)(x + ((size_t)(b*CC) + g*16)*NN);
    const int M4 = (16*NN)/4;
    float s = 0.f, s2 = 0.f;
    for (int i = threadIdx.x; i < M4; i += 256) {
        float4 v = p[i];
        s  += v.x + v.y + v.z + v.w;
        s2 += v.x*v.x + v.y*v.y + v.z*v.z + v.w*v.w;
    }
    #pragma unroll
    for (int o = 16; o; o >>= 1) {
        s  += __shfl_xor_sync(0xffffffffu, s,  o);
        s2 += __shfl_xor_sync(0xffffffffu, s2, o);
    }
    if ((threadIdx.x & 31) == 0) { rs[threadIdx.x>>5] = s; rs2[threadIdx.x>>5] = s2; }
    __syncthreads();
    if (threadIdx.x == 0) {
        float ts = 0.f, ts2 = 0.f;
        #pragma unroll
        for (int i = 0; i < 8; i++) { ts += rs[i]; ts2 += rs2[i]; }
        const float M = 16.f*NN;
        float mean = ts / M;
        float var  = ts2 / M - mean*mean;
        smean = mean;
        srstd = rsqrtf(var + 1e-5f);
    }
    __syncthreads();
    if (threadIdx.x < 16) {
        int c = g*16 + threadIdx.x;
        float w = nw[c];
        d_scl[b*CC + c] = srstd * w;
        d_sht[b*CC + c] = nb[c] - smean * srstd * w;
    }
}

// ---------------- K2: fused normalize + QKV GEMM, M-tile 64, 2 CTA/SM ----------------
__global__ __launch_bounds__(256) void k_qkv(const float* __restrict__ x,
                                             const float* __restrict__ qkvb) {
    extern __shared__ char sm[];
    __nv_bfloat16* As = (__nv_bfloat16*)sm;                 // [64][LDH]
    __nv_bfloat16* Bs = As + 64*LDH;                        // [128][LDH]
    float*         Cs = (float*)(Bs + 128*LDH);             // [64][LDF] row-major
    const int nt = blockIdx.x, b = blockIdx.y, tid = threadIdx.x;
    const int nbase = nt*64;

    // load + normalize + transpose A (64 n-rows x 128 c)
    {
        int c = tid >> 1, nh = tid & 1;
        const float4* xp = (const float4*)(x + ((size_t)(b*CC) + c)*NN + nbase + nh*32);
        float sc = d_scl[b*CC + c], sh = d_sht[b*CC + c];
        #pragma unroll
        for (int i = 0; i < 8; i++) {
            float4 v = xp[i];
            int n = nh*32 + i*4;
            As[(n+0)*LDH + c] = __float2bfloat16(v.x*sc + sh);
            As[(n+1)*LDH + c] = __float2bfloat16(v.y*sc + sh);
            As[(n+2)*LDH + c] = __float2bfloat16(v.z*sc + sh);
            As[(n+3)*LDH + c] = __float2bfloat16(v.w*sc + sh);
        }
    }

    const int w = tid >> 5, wr = w >> 2, wc = w & 3;   // rows wr*32, cols wc*32
    for (int ot = 0; ot < 3; ot++) {
        __syncthreads();
        {
            int o = tid >> 1, ch = tid & 1;
            const uint2* wp = (const uint2*)(d_wqkv + (ot*128 + o)*CC + ch*64);
            uint2* dp = (uint2*)(Bs + o*LDH + ch*64);
            #pragma unroll
            for (int i = 0; i < 16; i++) dp[i] = wp[i];
        }
        __syncthreads();
        #pragma unroll
        for (int i = 0; i < 2; i++) {
            FragC acc[2];
            #pragma unroll
            for (int jj = 0; jj < 2; jj++) wmma::fill_fragment(acc[jj], 0.f);
            #pragma unroll
            for (int k = 0; k < 8; k++) {
                FragA a; wmma::load_matrix_sync(a, As + (wr*32 + i*16)*LDH + k*16, LDH);
                #pragma unroll
                for (int jj = 0; jj < 2; jj++) {
                    FragBc bfr; wmma::load_matrix_sync(bfr, Bs + (wc*32 + jj*16)*LDH + k*16, LDH);
                    wmma::mma_sync(acc[jj], a, bfr, acc[jj]);
                }
            }
            #pragma unroll
            for (int jj = 0; jj < 2; jj++)
                wmma::store_matrix_sync(Cs + (wr*32 + i*16)*LDF + wc*32 + jj*16, acc[jj], LDF, wmma::mem_row_major);
        }
        __syncthreads();
        // write q/k/v bf16 with bias, vectorized (uint4 = 8 bf16)
        __nv_bfloat16* dst = (ot == 0) ? d_q : (ot == 1) ? d_k : d_v;
        {
            int n = tid >> 2, oh = tid & 3;
            __nv_bfloat16* op = dst + ((size_t)(b*NN) + nbase + n)*CC + oh*32;
            const float4* cp = (const float4*)(Cs + n*LDF + oh*32);
            const float4* bp = (const float4*)(qkvb + ot*128 + oh*32);
            #pragma unroll
            for (int g2 = 0; g2 < 4; g2++) {
                float4 a = cp[2*g2], c2 = cp[2*g2+1];
                float4 b0 = bp[2*g2], b1 = bp[2*g2+1];
                uint4 wv;
                wv.x = packbf2(a.x + b0.x,  a.y + b0.y);
                wv.y = packbf2(a.z + b0.z,  a.w + b0.w);
                wv.z = packbf2(c2.x + b1.x, c2.y + b1.y);
                wv.w = packbf2(c2.z + b1.z, c2.w + b1.w);
                *(uint4*)(op + 8*g2) = wv;
            }
        }
    }
}

// ---------------- K3: attention — register FA2, pipelined slices ----------------
// CTA: 256 thr (8 warps), q-tile 256 (32 rows/warp), kv-tile 128, kv-split 2.
// smem: sQ 64KB | sK0 32KB | sK1 32KB | sV0 32KB | sV1 32KB = 192KB.

__device__ __forceinline__ void load_tile128(uint32_t sbase, const __nv_bfloat16* g, int tid) {
    #pragma unroll
    for (int j = 0; j < 8; j++) {
        int id = tid + 256*j;
        int row = id >> 4, c = id & 15;
        cpa16(sbase + row*256 + ((c ^ (row & 7)) << 4), g + row*CC + c*8);
    }
}

__device__ __forceinline__ void compute_S(uint32_t sKb, int s, int lane,
                                          const uint32_t qf[2][8][4],
                                          float sc[2][2][4]) {
    const int r8 = lane & 7;
    #pragma unroll
    for (int rf = 0; rf < 2; rf++)
        #pragma unroll
        for (int nh = 0; nh < 2; nh++)
            #pragma unroll
            for (int e = 0; e < 4; e++) sc[rf][nh][e] = 0.f;
    #pragma unroll
    for (int kb2 = 0; kb2 < 4; kb2++) {
        uint32_t kf0[4], kf1[4];
        int ch = 4*kb2 + (lane >> 3);
        ldsm4(kf0, sKb + (s*16 +     r8)*256 + ((ch ^ r8) << 4));
        ldsm4(kf1, sKb + (s*16 + 8 + r8)*256 + ((ch ^ r8) << 4));
        #pragma unroll
        for (int rf = 0; rf < 2; rf++) {
            mma16816(sc[rf][0], qf[rf][2*kb2],     kf0);
            mma16816(sc[rf][0], qf[rf][2*kb2 + 1], kf0 + 2);
            mma16816(sc[rf][1], qf[rf][2*kb2],     kf1);
            mma16816(sc[rf][1], qf[rf][2*kb2 + 1], kf1 + 2);
        }
    }
}

__device__ __forceinline__ void compute_PV(uint32_t sVb, int s, int lane,
                                           const uint32_t pk[2][4],
                                           float o[2][16][4]) {
    const int r8 = lane & 7, hs = (lane >> 3) & 1, q16 = lane >> 4;
    #pragma unroll
    for (int cf = 0; cf < 8; cf++) {
        uint32_t vf[4];
        int ch = 2*cf + q16;
        ldsm4t(vf, sVb + (s*16 + hs*8 + r8)*256 + ((ch ^ r8) << 4));
        #pragma unroll
        for (int rf = 0; rf < 2; rf++) {
            mma16816(o[rf][2*cf],     pk[rf], vf);
            mma16816(o[rf][2*cf + 1], pk[rf], vf + 2);
        }
    }
}

__global__ __launch_bounds__(256) void k_attn() {
    extern __shared__ char sm[];
    const int tid = threadIdx.x, lane = tid & 31, w = tid >> 5;
    const int qt = blockIdx.x, ks = blockIdx.y, b = blockIdx.z;
    const uint32_t sb = smem_u32(sm);
    const uint32_t sQ = sb;
    const uint32_t sK[2] = { sb + 65536,  sb + 98304 };
    const uint32_t sV[2] = { sb + 131072, sb + 163840 };

    const __nv_bfloat16* gq = d_q + ((size_t)(b*NN) + qt*256)*CC;
    const __nv_bfloat16* gk = d_k + ((size_t)(b*NN) + ks*2048)*CC;
    const __nv_bfloat16* gv = d_v + ((size_t)(b*NN) + ks*2048)*CC;

    #pragma unroll
    for (int j = 0; j < 16; j++) {
        int id = tid + 256*j;
        int row = id >> 4, c = id & 15;
        cpa16(sQ + row*256 + ((c ^ (row & 7)) << 4), gq + row*CC + c*8);
    }
    load_tile128(sK[0], gk, tid);
    load_tile128(sV[0], gv, tid);
    CP_COMMIT();
    load_tile128(sK[1], gk + (size_t)128*CC, tid);
    load_tile128(sV[1], gv + (size_t)128*CC, tid);
    CP_COMMIT();

    const int r8 = lane & 7;
    const int hs = (lane >> 3) & 1;
    const int q16 = lane >> 4;

    CP_WAIT(1);
    __syncthreads();

    uint32_t qf[2][8][4];
    #pragma unroll
    for (int rf = 0; rf < 2; rf++)
        #pragma unroll
        for (int kb = 0; kb < 8; kb++) {
            int row = w*32 + rf*16 + hs*8 + r8;
            int ch = 2*kb + q16;
            ldsm4(qf[rf][kb], sQ + row*256 + ((ch ^ r8) << 4));
        }

    float o[2][16][4];
    #pragma unroll
    for (int rf = 0; rf < 2; rf++)
        #pragma unroll
        for (int cf = 0; cf < 16; cf++)
            #pragma unroll
            for (int e = 0; e < 4; e++) o[rf][cf][e] = 0.f;
    float l[2][2] = {{0.f, 0.f}, {0.f, 0.f}};
    const float sl2e = 0.12751744f;     // (1/sqrt(128)) * log2(e)

    #pragma unroll 1
    for (int it = 0; it < 16; it++) {
        const int bi = it & 1;
        if (it > 0) { CP_WAIT(1); __syncthreads(); }

        float sc[2][2][4];
        compute_S(sK[bi], 0, lane, qf, sc);

        #pragma unroll
        for (int s = 0; s < 8; s++) {
            uint32_t pk[2][4];
            #pragma unroll
            for (int rf = 0; rf < 2; rf++) {
                #pragma unroll
                for (int nh = 0; nh < 2; nh++)
                    #pragma unroll
                    for (int e = 0; e < 4; e++)
                        sc[rf][nh][e] = ex2f(sc[rf][nh][e]*sl2e);
                l[rf][0] += sc[rf][0][0] + sc[rf][0][1] + sc[rf][1][0] + sc[rf][1][1];
                l[rf][1] += sc[rf][0][2] + sc[rf][0][3] + sc[rf][1][2] + sc[rf][1][3];
                pk[rf][0] = packbf2(sc[rf][0][0], sc[rf][0][1]);
                pk[rf][1] = packbf2(sc[rf][0][2], sc[rf][0][3]);
                pk[rf][2] = packbf2(sc[rf][1][0], sc[rf][1][1]);
                pk[rf][3] = packbf2(sc[rf][1][2], sc[rf][1][3]);
            }
            if (s < 7) compute_S(sK[bi], s + 1, lane, qf, sc);
            compute_PV(sV[bi], s, lane, pk, o);
        }

        __syncthreads();
        if (it + 2 < 16) {
            load_tile128(sK[bi], gk + (size_t)(it + 2)*128*CC, tid);
            load_tile128(sV[bi], gv + (size_t)(it + 2)*128*CC, tid);
        }
        CP_COMMIT();
    }

    // ---- epilogue: write unnormalized fp32 partial O + partial l ----
    const int grp = lane >> 2, tc = lane & 3;
    float* op = d_op + (((size_t)ks*BB + b)*NN + qt*256 + w*32)*CC;
    #pragma unroll
    for (int rf = 0; rf < 2; rf++)
        #pragma unroll
        for (int cf = 0; cf < 16; cf++) {
            int col = cf*8 + 2*tc;
            *(float2*)(op + (rf*16 + grp    )*CC + col) = make_float2(o[rf][cf][0], o[rf][cf][1]);
            *(float2*)(op + (rf*16 + grp + 8)*CC + col) = make_float2(o[rf][cf][2], o[rf][cf][3]);
        }
    #pragma unroll
    for (int rf = 0; rf < 2; rf++)
        #pragma unroll
        for (int h = 0; h < 2; h++) {
            float v = l[rf][h];
            v += __shfl_xor_sync(0xffffffffu, v, 1);
            v += __shfl_xor_sync(0xffffffffu, v, 2);
            if (tc == 0)
                d_l[((size_t)ks*BB + b)*NN + qt*256 + w*32 + rf*16 + grp + 8*h] = v;
        }
}

// ---------------- K4: combine + proj GEMM + residual, M-tile 64, 2 CTA/SM ----------------
__global__ __launch_bounds__(256) void k_proj(const float* __restrict__ x,
                                              const float* __restrict__ projb,
                                              float* __restrict__ out) {
    extern __shared__ char sm[];
    __nv_bfloat16* As = (__nv_bfloat16*)sm;                 // [64][LDH]
    __nv_bfloat16* Bs = As + 64*LDH;                        // [128][LDH]
    float*         Cs = (float*)(Bs + 128*LDH);             // [128][LDC] col-major (o rows)
    const int nt = blockIdx.x, b = blockIdx.y, tid = threadIdx.x;
    const int nbase = nt*64;

    // A = (O0 + O1) / (l0 + l1), bf16 (64 n-rows x 128 c)
    {
        int n = tid >> 2, hh = tid & 3;
        size_t base = ((size_t)(b*NN) + nbase + n)*CC + hh*32;
        const float4* p0 = (const float4*)(d_op + base);
        const float4* p1 = (const float4*)(d_op + (size_t)BB*NN*CC + base);
        float inv = 1.f / (d_l[(size_t)b*NN + nbase + n] +
                           d_l[(size_t)BB*NN + b*NN + nbase + n]);
        uint32_t* ap = (uint32_t*)(As + n*LDH + hh*32);
        #pragma unroll
        for (int i = 0; i < 8; i++) {
            float4 a = p0[i], c = p1[i];
            ap[2*i]   = packbf2((a.x + c.x)*inv, (a.y + c.y)*inv);
            ap[2*i+1] = packbf2((a.z + c.z)*inv, (a.w + c.w)*inv);
        }
    }
    {
        int o = tid >> 1, ch = tid & 1;
        const uint2* wp = (const uint2*)(d_wproj + o*CC + ch*64);
        uint2* dp = (uint2*)(Bs + o*LDH + ch*64);
        #pragma unroll
        for (int i = 0; i < 16; i++) dp[i] = wp[i];
    }
    __syncthreads();

    const int w = tid >> 5, wr = w >> 2, wc = w & 3;
    #pragma unroll
    for (int i = 0; i < 2; i++) {
        FragC acc[2];
        #pragma unroll
        for (int jj = 0; jj < 2; jj++) wmma::fill_fragment(acc[jj], 0.f);
        #pragma unroll
        for (int k = 0; k < 8; k++) {
            FragA a; wmma::load_matrix_sync(a, As + (wr*32 + i*16)*LDH + k*16, LDH);
            #pragma unroll
            for (int jj = 0; jj < 2; jj++) {
                FragBc bfr; wmma::load_matrix_sync(bfr, Bs + (wc*32 + jj*16)*LDH + k*16, LDH);
                wmma::mma_sync(acc[jj], a, bfr, acc[jj]);
            }
        }
        // col-major: element (n_row, o_col) -> Cs[o_col*LDC + n_row]
        #pragma unroll
        for (int jj = 0; jj < 2; jj++)
            wmma::store_matrix_sync(Cs + (wc*32 + jj*16)*LDC + wr*32 + i*16, acc[jj], LDC, wmma::mem_col_major);
    }
    __syncthreads();
    // out[b][c][n] = x + proj + bias (contiguous in n now)
    {
        int c = tid >> 1, nh = tid & 1;
        const float4* xp = (const float4*)(x + ((size_t)(b*CC) + c)*NN + nbase + nh*32);
        float4* op = (float4*)(out + ((size_t)(b*CC) + c)*NN + nbase + nh*32);
        const float4* cp = (const float4*)(Cs + c*LDC + nh*32);
        float pb = projb[c];
        #pragma unroll
        for (int i = 0; i < 8; i++) {
            float4 xv = xp[i], cv = cp[i];
            op[i] = make_float4(xv.x + pb + cv.x, xv.y + pb + cv.y,
                                xv.z + pb + cv.z, xv.w + pb + cv.w);
        }
    }
}

// ---------------- launcher ----------------
extern "C" void kernel_launch(void* const* d_in, const int* in_sizes, int n_in,
                              void* d_out, int out_size) {
    const float* x     = (const float*)d_in[0];
    const float* nw    = (const float*)d_in[1];
    const float* nb    = (const float*)d_in[2];
    const float* qkvw  = (const float*)d_in[3];
    const float* qkvb  = (const float*)d_in[4];
    const float* projw = (const float*)d_in[5];
    const float* projb = (const float*)d_in[6];
    float* out = (float*)d_out;

    const int SM_QKV  = 64*LDH*2 + 128*LDH*2 + 64*LDF*4;   // 86016
    const int SM_PROJ = 64*LDH*2 + 128*LDH*2 + 128*LDC*4;  // 87040
    const int SM_ATTN = 65536 + 4*32768;                   // 196608

    cudaFuncSetAttribute(k_qkv,  cudaFuncAttributeMaxDynamicSharedMemorySize, SM_QKV);
    cudaFuncSetAttribute(k_attn, cudaFuncAttributeMaxDynamicSharedMemorySize, SM_ATTN);
    cudaFuncSetAttribute(k_proj, cudaFuncAttributeMaxDynamicSharedMemorySize, SM_PROJ);

    k_prep<<<224, 256>>>(x, nw, nb, qkvw, projw);
    k_qkv<<<dim3(64, BB), 256, SM_QKV>>>(x, qkvb);
    k_attn<<<dim3(16, 2, BB), 256, SM_ATTN>>>();
    k_proj<<<dim3(64, BB), 256, SM_PROJ>>>(x, projb, out);
}